// round 1
// baseline (speedup 1.0000x reference)
#include <cuda_runtime.h>
#include <cuda_bf16.h>
#include <cstdint>

typedef unsigned long long u64;

// ---------------------------------------------------------------------------
// Problem constants
// ---------------------------------------------------------------------------
#define SEQ   512
#define BATCH 64
#define HID   1024
#define G4    4096            // 4*HID
#define MROWS (SEQ * BATCH)   // 32768

// ---------------------------------------------------------------------------
// Scratch (device globals — no allocation allowed)
// ---------------------------------------------------------------------------
__device__ float g_proj[(size_t)MROWS * G4];   // [T*B, 4H]  x-projection (512 MB)
__device__ float g_out0[(size_t)MROWS * HID];  // layer-0 outputs [T*B, H] (128 MB)
__device__ float g_hT[2][HID * BATCH];         // double-buffered h, TRANSPOSED [j][b]
__device__ unsigned g_bar;                     // grid barrier counter

// ---------------------------------------------------------------------------
// f32x2 packed-FMA helpers (FFMA2 — 2x fp32 FMA throughput, exact semantics)
// ---------------------------------------------------------------------------
__device__ __forceinline__ u64 pack2(float x, float y) {
    u64 r; asm("mov.b64 %0, {%1,%2};" : "=l"(r) : "f"(x), "f"(y)); return r;
}
__device__ __forceinline__ void unpack2(u64 v, float& x, float& y) {
    asm("mov.b64 {%0,%1}, %2;" : "=f"(x), "=f"(y) : "l"(v));
}
__device__ __forceinline__ u64 ffma2(u64 a, u64 b, u64 c) {
    u64 d; asm("fma.rn.f32x2 %0, %1, %2, %3;" : "=l"(d) : "l"(a), "l"(b), "l"(c));
    return d;
}

__device__ __forceinline__ float sigmoidf_(float x) {
    return 1.0f / (1.0f + __expf(-x));
}
__device__ __forceinline__ float tanhf_(float x) {
    return 2.0f / (1.0f + __expf(-2.0f * x)) - 1.0f;
}

// ---------------------------------------------------------------------------
// Zero h state + barrier counter
// ---------------------------------------------------------------------------
__global__ void zero_state_kernel() {
    int i = blockIdx.x * blockDim.x + threadIdx.x;
    if (i == 0) g_bar = 0u;
    float4* p = reinterpret_cast<float4*>(&g_hT[0][0]);
    if (i < (2 * HID * BATCH) / 4) p[i] = make_float4(0.f, 0.f, 0.f, 0.f);
}

// ---------------------------------------------------------------------------
// SGEMM + bias: g_proj[m,n] = sum_k A[m,k] * W[n,k] + b1[n] + b2[n]
// A: [32768,1024] row-major (x, or g_out0 if Ain==nullptr). W: [4096,1024].
// Tiles 128x128x16, 256 threads, 8x8 per thread, FFMA2 pairs along n.
// ---------------------------------------------------------------------------
__global__ __launch_bounds__(256, 2) void sgemm_bias_kernel(
    const float* __restrict__ Ain,
    const float* __restrict__ Bw,
    const float* __restrict__ bias1,
    const float* __restrict__ bias2)
{
    const float* A = Ain ? Ain : g_out0;
    __shared__ float As[16 * 128];
    __shared__ float Bs[16 * 128];

    const int tid = threadIdx.x;
    const int tx = tid & 15;
    const int ty = tid >> 4;
    const int m0 = blockIdx.y * 128;
    const int n0 = blockIdx.x * 128;
    const int ldRow = tid >> 2;          // 0..63
    const int ldCol = (tid & 3) << 2;    // 0,4,8,12

    u64 acc[8][4];
#pragma unroll
    for (int i = 0; i < 8; i++)
#pragma unroll
        for (int jp = 0; jp < 4; jp++) acc[i][jp] = 0ULL;

    for (int kt = 0; kt < 1024; kt += 16) {
#pragma unroll
        for (int r = 0; r < 128; r += 64) {
            float4 av = *reinterpret_cast<const float4*>(
                &A[(size_t)(m0 + ldRow + r) * 1024 + kt + ldCol]);
            As[(ldCol + 0) * 128 + ldRow + r] = av.x;
            As[(ldCol + 1) * 128 + ldRow + r] = av.y;
            As[(ldCol + 2) * 128 + ldRow + r] = av.z;
            As[(ldCol + 3) * 128 + ldRow + r] = av.w;
            float4 bv = *reinterpret_cast<const float4*>(
                &Bw[(size_t)(n0 + ldRow + r) * 1024 + kt + ldCol]);
            Bs[(ldCol + 0) * 128 + ldRow + r] = bv.x;
            Bs[(ldCol + 1) * 128 + ldRow + r] = bv.y;
            Bs[(ldCol + 2) * 128 + ldRow + r] = bv.z;
            Bs[(ldCol + 3) * 128 + ldRow + r] = bv.w;
        }
        __syncthreads();

#pragma unroll
        for (int kk = 0; kk < 16; kk++) {
            float4 a0 = *reinterpret_cast<const float4*>(&As[kk * 128 + ty * 8]);
            float4 a1 = *reinterpret_cast<const float4*>(&As[kk * 128 + ty * 8 + 4]);
            ulonglong2 q0 = *reinterpret_cast<const ulonglong2*>(&Bs[kk * 128 + tx * 8]);
            ulonglong2 q1 = *reinterpret_cast<const ulonglong2*>(&Bs[kk * 128 + tx * 8 + 4]);
            u64 bb[4] = {q0.x, q0.y, q1.x, q1.y};
            float aa[8] = {a0.x, a0.y, a0.z, a0.w, a1.x, a1.y, a1.z, a1.w};
#pragma unroll
            for (int i = 0; i < 8; i++) {
                u64 ap = pack2(aa[i], aa[i]);
#pragma unroll
                for (int jp = 0; jp < 4; jp++)
                    acc[i][jp] = ffma2(ap, bb[jp], acc[i][jp]);
            }
        }
        __syncthreads();
    }

#pragma unroll
    for (int i = 0; i < 8; i++) {
        const int row = m0 + ty * 8 + i;
#pragma unroll
        for (int jp = 0; jp < 4; jp++) {
            float x, y;
            unpack2(acc[i][jp], x, y);
            const int col = n0 + tx * 8 + jp * 2;
            g_proj[(size_t)row * G4 + col]     = x + bias1[col]     + bias2[col];
            g_proj[(size_t)row * G4 + col + 1] = y + bias1[col + 1] + bias2[col + 1];
        }
    }
}

// ---------------------------------------------------------------------------
// Persistent LSTM recurrence. 128 blocks x 128 threads, one block per 8 hidden
// units (all 4 gates). W_hh slice (32x1024) resident in SMEM for all 512 steps.
// Grid barrier per step via atomic counter; h kept transposed [j][b] in global.
// Thread = 1 unit x 4 batch rows; f32x2 packed FMAs over batch pairs.
// ---------------------------------------------------------------------------
#define WPITCH 1028                      // 1028*4B = 16B-aligned rows, bank-spread
#define BKR 256                          // k-tile of h staged in smem
#define REC_SMEM ((32 * WPITCH + BKR * BATCH) * 4)

__global__ __launch_bounds__(128, 1) void lstm_layer_kernel(
    const float* __restrict__ W,   // W_hh [4096,1024]
    float* __restrict__ out,       // [T*B, H] layer output (nullptr -> g_out0)
    float* __restrict__ hn,        // [B, H]
    float* __restrict__ cn)        // [B, H]
{
    extern __shared__ float sm[];
    float* Wsm = sm;                       // [32][WPITCH], row index = u*4 + g
    float* Hsm = sm + 32 * WPITCH;         // [BKR][64]

    float* outp = out ? out : g_out0;

    const int tid = threadIdx.x;
    const int u  = tid >> 4;               // 0..7  (unit within block)
    const int b0 = (tid & 15) * 4;         // batch base (4 rows per thread)
    const int j  = blockIdx.x * 8 + u;     // global hidden unit

    // Stage this block's W_hh slice into SMEM once.
    {
        const int warp = tid >> 5, lane = tid & 31;
        for (int r = warp; r < 32; r += 4) {
            const int uu = r >> 2, gg = r & 3;
            const float* src = W + ((size_t)gg * HID + blockIdx.x * 8 + uu) * HID;
            float* dst = Wsm + r * WPITCH;
            for (int k = lane * 4; k < HID; k += 32 * 4)
                *reinterpret_cast<float4*>(&dst[k]) =
                    *reinterpret_cast<const float4*>(&src[k]);
        }
    }
    __syncthreads();

    const float* wp0 = Wsm + (u * 4 + 0) * WPITCH;
    const float* wp1 = Wsm + (u * 4 + 1) * WPITCH;
    const float* wp2 = Wsm + (u * 4 + 2) * WPITCH;
    const float* wp3 = Wsm + (u * 4 + 3) * WPITCH;

    float cst[4] = {0.f, 0.f, 0.f, 0.f};

    for (int s = 0; s < SEQ; s++) {
        // Prefetch x-projection values (DRAM; hidden under the k-loop).
        float pv[4][4];
        const float* prb = g_proj + (size_t)s * BATCH * G4;
#pragma unroll
        for (int bi = 0; bi < 4; bi++)
#pragma unroll
            for (int g = 0; g < 4; g++)
                pv[g][bi] = __ldg(&prb[(size_t)(b0 + bi) * G4 + g * HID + j]);

        u64 acc[4][2];
#pragma unroll
        for (int g = 0; g < 4; g++) { acc[g][0] = 0ULL; acc[g][1] = 0ULL; }

        const float* hin = g_hT[s & 1];

        for (int kt = 0; kt < HID; kt += BKR) {
            __syncthreads();   // protect Hsm from previous tile's readers
            // Stage h tile: straight coalesced copy ([j][b] layout). L2-fresh.
            for (int i = tid * 4; i < BKR * BATCH; i += 128 * 4) {
                float4 v = __ldcg(reinterpret_cast<const float4*>(
                    &hin[(size_t)kt * BATCH + i]));
                *reinterpret_cast<float4*>(&Hsm[i]) = v;
            }
            __syncthreads();

#pragma unroll 4
            for (int k = 0; k < BKR; k++) {
                float4 h4 = *reinterpret_cast<const float4*>(&Hsm[k * BATCH + b0]);
                u64 hA = pack2(h4.x, h4.y);
                u64 hB = pack2(h4.z, h4.w);
                const int kk = kt + k;
                u64 w0 = pack2(wp0[kk], wp0[kk]);
                u64 w1 = pack2(wp1[kk], wp1[kk]);
                u64 w2 = pack2(wp2[kk], wp2[kk]);
                u64 w3 = pack2(wp3[kk], wp3[kk]);
                acc[0][0] = ffma2(hA, w0, acc[0][0]);
                acc[0][1] = ffma2(hB, w0, acc[0][1]);
                acc[1][0] = ffma2(hA, w1, acc[1][0]);
                acc[1][1] = ffma2(hB, w1, acc[1][1]);
                acc[2][0] = ffma2(hA, w2, acc[2][0]);
                acc[2][1] = ffma2(hB, w2, acc[2][1]);
                acc[3][0] = ffma2(hA, w3, acc[3][0]);
                acc[3][1] = ffma2(hB, w3, acc[3][1]);
            }
        }

        // Gates + elementwise update for this thread's 4 batch rows.
        float gate[4][4];
#pragma unroll
        for (int g = 0; g < 4; g++) {
            unpack2(acc[g][0], gate[g][0], gate[g][1]);
            unpack2(acc[g][1], gate[g][2], gate[g][3]);
        }

        float hv[4];
#pragma unroll
        for (int bi = 0; bi < 4; bi++) {
            float gi = sigmoidf_(gate[0][bi] + pv[0][bi]);
            float gf = sigmoidf_(gate[1][bi] + pv[1][bi]);
            float gg = tanhf_  (gate[2][bi] + pv[2][bi]);
            float go = sigmoidf_(gate[3][bi] + pv[3][bi]);
            float cnew = gf * cst[bi] + gi * gg;
            cst[bi] = cnew;
            hv[bi] = go * tanhf_(cnew);
        }

        // Publish h (transposed buffer + layer output).
        float* hout = g_hT[(s + 1) & 1];
        *reinterpret_cast<float4*>(&hout[(size_t)j * BATCH + b0]) =
            make_float4(hv[0], hv[1], hv[2], hv[3]);
#pragma unroll
        for (int bi = 0; bi < 4; bi++)
            outp[((size_t)s * BATCH + b0 + bi) * HID + j] = hv[bi];

        if (s == SEQ - 1) {
#pragma unroll
            for (int bi = 0; bi < 4; bi++) {
                hn[(size_t)(b0 + bi) * HID + j] = hv[bi];
                cn[(size_t)(b0 + bi) * HID + j] = cst[bi];
            }
        }

        // Grid barrier (all 128 blocks co-resident on 148 SMs).
        __threadfence();
        __syncthreads();
        if (tid == 0) {
            atomicAdd(&g_bar, 1u);
            const unsigned target = (unsigned)(s + 1) * gridDim.x;
            while (atomicAdd(&g_bar, 0u) < target) __nanosleep(64);
            __threadfence();
        }
        __syncthreads();
    }
}

// ---------------------------------------------------------------------------
// Launch
// ---------------------------------------------------------------------------
extern "C" void kernel_launch(void* const* d_in, const int* in_sizes, int n_in,
                              void* d_out, int out_size)
{
    const float* x     = (const float*)d_in[0];
    const float* Wih0  = (const float*)d_in[1];
    const float* Whh0  = (const float*)d_in[2];
    const float* bih0  = (const float*)d_in[3];
    const float* bhh0  = (const float*)d_in[4];
    const float* Wih1  = (const float*)d_in[5];
    const float* Whh1  = (const float*)d_in[6];
    const float* bih1  = (const float*)d_in[7];
    const float* bhh1  = (const float*)d_in[8];

    float* out1 = (float*)d_out;                                // [512,64,1024]
    float* hn   = out1 + (size_t)SEQ * BATCH * HID;             // [2,64,1024]
    float* cn   = hn + 2 * BATCH * HID;                         // [2,64,1024]

    cudaFuncSetAttribute(lstm_layer_kernel,
                         cudaFuncAttributeMaxDynamicSharedMemorySize, REC_SMEM);

    dim3 ggrid(G4 / 128, MROWS / 128);   // (32, 256)

    // Layer 0
    zero_state_kernel<<<128, 256>>>();
    sgemm_bias_kernel<<<ggrid, 256>>>(x, Wih0, bih0, bhh0);
    lstm_layer_kernel<<<128, 128, REC_SMEM>>>(Whh0, nullptr, hn, cn);

    // Layer 1
    zero_state_kernel<<<128, 256>>>();
    sgemm_bias_kernel<<<ggrid, 256>>>(nullptr, Wih1, bih1, bhh1);
    lstm_layer_kernel<<<128, 128, REC_SMEM>>>(Whh1, out1,
                                              hn + BATCH * HID,
                                              cn + BATCH * HID);
}

// round 3
// speedup vs baseline: 1.2192x; 1.2192x over previous
#include <cuda_runtime.h>
#include <cuda_bf16.h>
#include <cstdint>

typedef unsigned long long u64;

// ---------------------------------------------------------------------------
// Problem constants
// ---------------------------------------------------------------------------
#define SEQ   512
#define BATCH 64
#define HID   1024
#define G4    4096            // 4*HID
#define MROWS (SEQ * BATCH)   // 32768

// ---------------------------------------------------------------------------
// Scratch (device globals — no allocation allowed)
// ---------------------------------------------------------------------------
__device__ float g_proj[(size_t)MROWS * G4];          // [T*B, 4H] x-projection
__device__ float g_out0[(size_t)MROWS * HID];         // layer-0 outputs
__device__ float g_hT[2][HID * BATCH];                // h double buffer, [j][b]
__device__ unsigned g_bar;                            // grid barrier counter
__device__ __nv_bfloat16 g_Ahi[(size_t)MROWS * HID];  // A split hi
__device__ __nv_bfloat16 g_Alo[(size_t)MROWS * HID];  // A split lo
__device__ __nv_bfloat16 g_Whi[(size_t)G4 * HID];     // W split hi
__device__ __nv_bfloat16 g_Wlo[(size_t)G4 * HID];     // W split lo

// ---------------------------------------------------------------------------
// Helpers
// ---------------------------------------------------------------------------
__device__ __forceinline__ uint32_t smem_u32(const void* p) {
    uint32_t a;
    asm("{ .reg .u64 t; cvta.to.shared.u64 t, %1; cvt.u32.u64 %0, t; }"
        : "=r"(a) : "l"(p));
    return a;
}
__device__ __forceinline__ void ldsm4(uint32_t* r, uint32_t addr) {
    asm volatile("ldmatrix.sync.aligned.m8n8.x4.shared.b16 {%0,%1,%2,%3}, [%4];"
                 : "=r"(r[0]), "=r"(r[1]), "=r"(r[2]), "=r"(r[3]) : "r"(addr));
}
__device__ __forceinline__ void ldsm2(uint32_t* r, uint32_t addr) {
    asm volatile("ldmatrix.sync.aligned.m8n8.x2.shared.b16 {%0,%1}, [%2];"
                 : "=r"(r[0]), "=r"(r[1]) : "r"(addr));
}
__device__ __forceinline__ void mma16816(float* c, const uint32_t* a, const uint32_t* b) {
    asm volatile("mma.sync.aligned.m16n8k16.row.col.f32.bf16.bf16.f32 "
                 "{%0,%1,%2,%3}, {%4,%5,%6,%7}, {%8,%9}, {%0,%1,%2,%3};"
                 : "+f"(c[0]), "+f"(c[1]), "+f"(c[2]), "+f"(c[3])
                 : "r"(a[0]), "r"(a[1]), "r"(a[2]), "r"(a[3]),
                   "r"(b[0]), "r"(b[1]));
}
#define CP_ASYNC16(sdst, gsrc) \
    asm volatile("cp.async.cg.shared.global [%0], [%1], 16;" :: "r"(sdst), "l"(gsrc))
#define CP_COMMIT() asm volatile("cp.async.commit_group;" ::: "memory")
#define CP_WAIT1()  asm volatile("cp.async.wait_group 1;" ::: "memory")

// f32x2 packed-FMA helpers (recurrence)
__device__ __forceinline__ u64 pack2(float x, float y) {
    u64 r; asm("mov.b64 %0, {%1,%2};" : "=l"(r) : "f"(x), "f"(y)); return r;
}
__device__ __forceinline__ void unpack2(u64 v, float& x, float& y) {
    asm("mov.b64 {%0,%1}, %2;" : "=f"(x), "=f"(y) : "l"(v));
}
__device__ __forceinline__ u64 ffma2(u64 a, u64 b, u64 c) {
    u64 d; asm("fma.rn.f32x2 %0, %1, %2, %3;" : "=l"(d) : "l"(a), "l"(b), "l"(c));
    return d;
}
__device__ __forceinline__ float sigmoidf_(float x) { return 1.0f / (1.0f + __expf(-x)); }
__device__ __forceinline__ float tanhf_(float x) { return 2.0f / (1.0f + __expf(-2.0f * x)) - 1.0f; }

// ---------------------------------------------------------------------------
// Zero h state + barrier counter
// ---------------------------------------------------------------------------
__global__ void zero_state_kernel() {
    int i = blockIdx.x * blockDim.x + threadIdx.x;
    if (i == 0) g_bar = 0u;
    float4* p = reinterpret_cast<float4*>(&g_hT[0][0]);
    if (i < (2 * HID * BATCH) / 4) p[i] = make_float4(0.f, 0.f, 0.f, 0.f);
}

// ---------------------------------------------------------------------------
// fp32 -> bf16 hi/lo split
// ---------------------------------------------------------------------------
__global__ void split_kernel(const float* __restrict__ src,
                             __nv_bfloat16* __restrict__ hi,
                             __nv_bfloat16* __restrict__ lo, int n4) {
    int i = blockIdx.x * blockDim.x + threadIdx.x;
    int stride = gridDim.x * blockDim.x;
    for (; i < n4; i += stride) {
        float4 v = reinterpret_cast<const float4*>(src)[i];
        __nv_bfloat16 h[4], l[4];
        float vv[4] = {v.x, v.y, v.z, v.w};
#pragma unroll
        for (int k = 0; k < 4; k++) {
            h[k] = __float2bfloat16_rn(vv[k]);
            l[k] = __float2bfloat16_rn(vv[k] - __bfloat162float(h[k]));
        }
        reinterpret_cast<uint2*>(hi)[i] = *reinterpret_cast<uint2*>(h);
        reinterpret_cast<uint2*>(lo)[i] = *reinterpret_cast<uint2*>(l);
    }
}

__global__ void split_out0_kernel(int n4) {
    int i = blockIdx.x * blockDim.x + threadIdx.x;
    int stride = gridDim.x * blockDim.x;
    for (; i < n4; i += stride) {
        float4 v = reinterpret_cast<const float4*>(g_out0)[i];
        __nv_bfloat16 h[4], l[4];
        float vv[4] = {v.x, v.y, v.z, v.w};
#pragma unroll
        for (int k = 0; k < 4; k++) {
            h[k] = __float2bfloat16_rn(vv[k]);
            l[k] = __float2bfloat16_rn(vv[k] - __bfloat162float(h[k]));
        }
        reinterpret_cast<uint2*>(g_Ahi)[i] = *reinterpret_cast<uint2*>(h);
        reinterpret_cast<uint2*>(g_Alo)[i] = *reinterpret_cast<uint2*>(l);
    }
}

// ---------------------------------------------------------------------------
// bf16x3 GEMM via mma.sync: g_proj[m,n] = sum_k A[m,k]*W[n,k] + b1[n] + b2[n]
// CTA tile 128x128, K staged 32 (cp.async double buffer). 8 warps (4m x 2n),
// warp tile 32x64. 3 passes per k16: Ahi*Whi + Ahi*Wlo + Alo*Whi.
// SMEM tiles [row][k32] bf16, pitch 40 bf16 (80B) -> conflict-free ldmatrix.
// ---------------------------------------------------------------------------
#define KSTG       32
#define NSTAGES    (HID / KSTG)          // 32
#define PITCH_B    80                    // bytes per row (40 bf16)
#define REG_BYTES  (128 * PITCH_B)       // 10240
#define STG_BYTES  (4 * REG_BYTES)       // 40960
#define GEMM_SMEM  (2 * STG_BYTES)       // 81920

__device__ __forceinline__ void stage_load(uint32_t sbase, int s, int m0, int n0,
                                           int tid) {
    const int kt = s * KSTG;
    const uint32_t dst = sbase + (s & 1) * STG_BYTES;
#pragma unroll
    for (int r = 0; r < 4; r++) {
        const __nv_bfloat16* src =
            (r == 0) ? g_Ahi : (r == 1) ? g_Alo : (r == 2) ? g_Whi : g_Wlo;
        const int rb = (r < 2) ? m0 : n0;
#pragma unroll
        for (int j = 0; j < 2; j++) {
            const int chunk = tid + j * 256;
            const int row = chunk >> 2;
            const int kc = chunk & 3;
            const void* g = src + (size_t)(rb + row) * HID + kt + kc * 8;
            const uint32_t sd = dst + r * REG_BYTES + row * PITCH_B + kc * 16;
            CP_ASYNC16(sd, g);
        }
    }
}

__global__ __launch_bounds__(256, 1) void mma_gemm_kernel(
    const float* __restrict__ bias1, const float* __restrict__ bias2)
{
    extern __shared__ char dsm[];
    __shared__ float s_bias[128];

    const int tid = threadIdx.x;
    const int wid = tid >> 5;
    const int lane = tid & 31;
    const int m0 = blockIdx.x * 128;   // m fastest -> W tile shared in L2
    const int n0 = blockIdx.y * 128;
    const int wm = (wid & 3) * 32;     // warp m offset in tile
    const int wn = (wid >> 2) * 64;    // warp n offset in tile

    const uint32_t sbase = smem_u32(dsm);

    if (tid < 128) s_bias[tid] = bias1[n0 + tid] + bias2[n0 + tid];

    float acc[2][8][4];
#pragma unroll
    for (int ma = 0; ma < 2; ma++)
#pragma unroll
        for (int nb = 0; nb < 8; nb++)
#pragma unroll
            for (int c = 0; c < 4; c++) acc[ma][nb][c] = 0.f;

    stage_load(sbase, 0, m0, n0, tid);
    CP_COMMIT();

    for (int s = 0; s < NSTAGES; s++) {
        if (s + 1 < NSTAGES) stage_load(sbase, s + 1, m0, n0, tid);
        CP_COMMIT();
        CP_WAIT1();
        __syncthreads();

        const uint32_t sb = sbase + (s & 1) * STG_BYTES;
        const uint32_t aHi = sb;
        const uint32_t aLo = sb + REG_BYTES;
        const uint32_t wHi = sb + 2 * REG_BYTES;
        const uint32_t wLo = sb + 3 * REG_BYTES;

#pragma unroll
        for (int kk = 0; kk < 2; kk++) {
            const uint32_t aoff = (lane & 15) * PITCH_B + (lane >> 4) * 16 + kk * 32;
            const uint32_t boff = (lane & 7) * PITCH_B + ((lane >> 3) & 1) * 16 + kk * 32;

            uint32_t ahi[2][4], alo[2][4];
            ldsm4(ahi[0], aHi + (wm + 0) * PITCH_B + aoff);
            ldsm4(ahi[1], aHi + (wm + 16) * PITCH_B + aoff);
            ldsm4(alo[0], aLo + (wm + 0) * PITCH_B + aoff);
            ldsm4(alo[1], aLo + (wm + 16) * PITCH_B + aoff);

            uint32_t whi[8][2], wlo[8][2];
#pragma unroll
            for (int nb = 0; nb < 8; nb++) {
                ldsm2(whi[nb], wHi + (wn + nb * 8) * PITCH_B + boff);
                ldsm2(wlo[nb], wLo + (wn + nb * 8) * PITCH_B + boff);
            }

#pragma unroll
            for (int ma = 0; ma < 2; ma++)
#pragma unroll
                for (int nb = 0; nb < 8; nb++) {
                    mma16816(acc[ma][nb], ahi[ma], whi[nb]);
                    mma16816(acc[ma][nb], ahi[ma], wlo[nb]);
                    mma16816(acc[ma][nb], alo[ma], whi[nb]);
                }
        }
        __syncthreads();
    }

    // Epilogue: C fragment (c0,c1)=row, (c2,c3)=row+8; cols (lane&3)*2, +1
#pragma unroll
    for (int ma = 0; ma < 2; ma++) {
        const int row = m0 + wm + ma * 16 + (lane >> 2);
#pragma unroll
        for (int nb = 0; nb < 8; nb++) {
            const int cloc = wn + nb * 8 + (lane & 3) * 2;
            const int col = n0 + cloc;
            const float b0 = s_bias[cloc], b1 = s_bias[cloc + 1];
            float2 v0 = make_float2(acc[ma][nb][0] + b0, acc[ma][nb][1] + b1);
            float2 v1 = make_float2(acc[ma][nb][2] + b0, acc[ma][nb][3] + b1);
            *reinterpret_cast<float2*>(&g_proj[(size_t)row * G4 + col]) = v0;
            *reinterpret_cast<float2*>(&g_proj[(size_t)(row + 8) * G4 + col]) = v1;
        }
    }
}

// ---------------------------------------------------------------------------
// Persistent LSTM recurrence (unchanged).
// ---------------------------------------------------------------------------
#define WPITCH 1028
#define BKR 256
#define REC_SMEM ((32 * WPITCH + BKR * BATCH) * 4)

__global__ __launch_bounds__(128, 1) void lstm_layer_kernel(
    const float* __restrict__ W,
    float* __restrict__ out,
    float* __restrict__ hn,
    float* __restrict__ cn)
{
    extern __shared__ float sm[];
    float* Wsm = sm;
    float* Hsm = sm + 32 * WPITCH;

    float* outp = out ? out : g_out0;

    const int tid = threadIdx.x;
    const int u  = tid >> 4;
    const int b0 = (tid & 15) * 4;
    const int j  = blockIdx.x * 8 + u;

    {
        const int warp = tid >> 5, lane = tid & 31;
        for (int r = warp; r < 32; r += 4) {
            const int uu = r >> 2, gg = r & 3;
            const float* src = W + ((size_t)gg * HID + blockIdx.x * 8 + uu) * HID;
            float* dst = Wsm + r * WPITCH;
            for (int k = lane * 4; k < HID; k += 32 * 4)
                *reinterpret_cast<float4*>(&dst[k]) =
                    *reinterpret_cast<const float4*>(&src[k]);
        }
    }
    __syncthreads();

    const float* wp0 = Wsm + (u * 4 + 0) * WPITCH;
    const float* wp1 = Wsm + (u * 4 + 1) * WPITCH;
    const float* wp2 = Wsm + (u * 4 + 2) * WPITCH;
    const float* wp3 = Wsm + (u * 4 + 3) * WPITCH;

    float cst[4] = {0.f, 0.f, 0.f, 0.f};

    for (int s = 0; s < SEQ; s++) {
        float pv[4][4];
        const float* prb = g_proj + (size_t)s * BATCH * G4;
#pragma unroll
        for (int bi = 0; bi < 4; bi++)
#pragma unroll
            for (int g = 0; g < 4; g++)
                pv[g][bi] = __ldg(&prb[(size_t)(b0 + bi) * G4 + g * HID + j]);

        u64 acc[4][2];
#pragma unroll
        for (int g = 0; g < 4; g++) { acc[g][0] = 0ULL; acc[g][1] = 0ULL; }

        const float* hin = g_hT[s & 1];

        for (int kt = 0; kt < HID; kt += BKR) {
            __syncthreads();
            for (int i = tid * 4; i < BKR * BATCH; i += 128 * 4) {
                float4 v = __ldcg(reinterpret_cast<const float4*>(
                    &hin[(size_t)kt * BATCH + i]));
                *reinterpret_cast<float4*>(&Hsm[i]) = v;
            }
            __syncthreads();

#pragma unroll 4
            for (int k = 0; k < BKR; k++) {
                float4 h4 = *reinterpret_cast<const float4*>(&Hsm[k * BATCH + b0]);
                u64 hA = pack2(h4.x, h4.y);
                u64 hB = pack2(h4.z, h4.w);
                const int kk = kt + k;
                u64 w0 = pack2(wp0[kk], wp0[kk]);
                u64 w1 = pack2(wp1[kk], wp1[kk]);
                u64 w2 = pack2(wp2[kk], wp2[kk]);
                u64 w3 = pack2(wp3[kk], wp3[kk]);
                acc[0][0] = ffma2(hA, w0, acc[0][0]);
                acc[0][1] = ffma2(hB, w0, acc[0][1]);
                acc[1][0] = ffma2(hA, w1, acc[1][0]);
                acc[1][1] = ffma2(hB, w1, acc[1][1]);
                acc[2][0] = ffma2(hA, w2, acc[2][0]);
                acc[2][1] = ffma2(hB, w2, acc[2][1]);
                acc[3][0] = ffma2(hA, w3, acc[3][0]);
                acc[3][1] = ffma2(hB, w3, acc[3][1]);
            }
        }

        float gate[4][4];
#pragma unroll
        for (int g = 0; g < 4; g++) {
            unpack2(acc[g][0], gate[g][0], gate[g][1]);
            unpack2(acc[g][1], gate[g][2], gate[g][3]);
        }

        float hv[4];
#pragma unroll
        for (int bi = 0; bi < 4; bi++) {
            float gi = sigmoidf_(gate[0][bi] + pv[0][bi]);
            float gf = sigmoidf_(gate[1][bi] + pv[1][bi]);
            float gg = tanhf_  (gate[2][bi] + pv[2][bi]);
            float go = sigmoidf_(gate[3][bi] + pv[3][bi]);
            float cnew = gf * cst[bi] + gi * gg;
            cst[bi] = cnew;
            hv[bi] = go * tanhf_(cnew);
        }

        float* hout = g_hT[(s + 1) & 1];
        *reinterpret_cast<float4*>(&hout[(size_t)j * BATCH + b0]) =
            make_float4(hv[0], hv[1], hv[2], hv[3]);
#pragma unroll
        for (int bi = 0; bi < 4; bi++)
            outp[((size_t)s * BATCH + b0 + bi) * HID + j] = hv[bi];

        if (s == SEQ - 1) {
#pragma unroll
            for (int bi = 0; bi < 4; bi++) {
                hn[(size_t)(b0 + bi) * HID + j] = hv[bi];
                cn[(size_t)(b0 + bi) * HID + j] = cst[bi];
            }
        }

        __threadfence();
        __syncthreads();
        if (tid == 0) {
            atomicAdd(&g_bar, 1u);
            const unsigned target = (unsigned)(s + 1) * gridDim.x;
            while (atomicAdd(&g_bar, 0u) < target) __nanosleep(64);
            __threadfence();
        }
        __syncthreads();
    }
}

// ---------------------------------------------------------------------------
// Launch
// ---------------------------------------------------------------------------
extern "C" void kernel_launch(void* const* d_in, const int* in_sizes, int n_in,
                              void* d_out, int out_size)
{
    const float* x     = (const float*)d_in[0];
    const float* Wih0  = (const float*)d_in[1];
    const float* Whh0  = (const float*)d_in[2];
    const float* bih0  = (const float*)d_in[3];
    const float* bhh0  = (const float*)d_in[4];
    const float* Wih1  = (const float*)d_in[5];
    const float* Whh1  = (const float*)d_in[6];
    const float* bih1  = (const float*)d_in[7];
    const float* bhh1  = (const float*)d_in[8];

    float* out1 = (float*)d_out;
    float* hn   = out1 + (size_t)SEQ * BATCH * HID;
    float* cn   = hn + 2 * BATCH * HID;

    cudaFuncSetAttribute(lstm_layer_kernel,
                         cudaFuncAttributeMaxDynamicSharedMemorySize, REC_SMEM);
    cudaFuncSetAttribute(mma_gemm_kernel,
                         cudaFuncAttributeMaxDynamicSharedMemorySize, GEMM_SMEM);

    __nv_bfloat16 *Ahi, *Alo, *Whi, *Wlo;
    cudaGetSymbolAddress((void**)&Ahi, g_Ahi);
    cudaGetSymbolAddress((void**)&Alo, g_Alo);
    cudaGetSymbolAddress((void**)&Whi, g_Whi);
    cudaGetSymbolAddress((void**)&Wlo, g_Wlo);

    dim3 mgrid(MROWS / 128, G4 / 128);   // (256, 32), m fastest

    // ---- Layer 0 ----
    split_kernel<<<2048, 256>>>(x, Ahi, Alo, (MROWS * HID) / 4);
    split_kernel<<<512, 256>>>(Wih0, Whi, Wlo, (G4 * HID) / 4);
    zero_state_kernel<<<128, 256>>>();
    mma_gemm_kernel<<<mgrid, 256, GEMM_SMEM>>>(bih0, bhh0);
    lstm_layer_kernel<<<128, 128, REC_SMEM>>>(Whh0, nullptr, hn, cn);

    // ---- Layer 1 ----
    split_out0_kernel<<<2048, 256>>>((MROWS * HID) / 4);
    split_kernel<<<512, 256>>>(Wih1, Whi, Wlo, (G4 * HID) / 4);
    zero_state_kernel<<<128, 256>>>();
    mma_gemm_kernel<<<mgrid, 256, GEMM_SMEM>>>(bih1, bhh1);
    lstm_layer_kernel<<<128, 128, REC_SMEM>>>(Whh1, out1,
                                              hn + BATCH * HID,
                                              cn + BATCH * HID);
}

// round 4
// speedup vs baseline: 2.3626x; 1.9378x over previous
#include <cuda_runtime.h>
#include <cuda_bf16.h>
#include <cstdint>

typedef unsigned long long u64;

// ---------------------------------------------------------------------------
// Problem constants
// ---------------------------------------------------------------------------
#define SEQ   512
#define BATCH 64
#define HID   1024
#define G4    4096            // 4*HID
#define MROWS (SEQ * BATCH)   // 32768

// ---------------------------------------------------------------------------
// Scratch (device globals — no allocation allowed)
// ---------------------------------------------------------------------------
__device__ float g_proj[(size_t)MROWS * G4];          // [T*B, 4H] x-projection
__device__ float g_out0[(size_t)MROWS * HID];         // layer-0 outputs
__device__ unsigned g_bar;                            // grid barrier counter
__device__ __align__(16) __nv_bfloat16 g_Ahi[(size_t)MROWS * HID];
__device__ __align__(16) __nv_bfloat16 g_Alo[(size_t)MROWS * HID];
__device__ __align__(16) __nv_bfloat16 g_Whi[(size_t)G4 * HID];
__device__ __align__(16) __nv_bfloat16 g_Wlo[(size_t)G4 * HID];
__device__ __align__(16) __nv_bfloat16 g_hhi[2][BATCH * HID];  // h hi, [b][j]
__device__ __align__(16) __nv_bfloat16 g_hlo[2][BATCH * HID];  // h lo, [b][j]

// ---------------------------------------------------------------------------
// Helpers
// ---------------------------------------------------------------------------
__device__ __forceinline__ uint32_t smem_u32(const void* p) {
    uint32_t a;
    asm("{ .reg .u64 t; cvta.to.shared.u64 t, %1; cvt.u32.u64 %0, t; }"
        : "=r"(a) : "l"(p));
    return a;
}
__device__ __forceinline__ void ldsm4(uint32_t* r, uint32_t addr) {
    asm volatile("ldmatrix.sync.aligned.m8n8.x4.shared.b16 {%0,%1,%2,%3}, [%4];"
                 : "=r"(r[0]), "=r"(r[1]), "=r"(r[2]), "=r"(r[3]) : "r"(addr));
}
__device__ __forceinline__ void ldsm2(uint32_t* r, uint32_t addr) {
    asm volatile("ldmatrix.sync.aligned.m8n8.x2.shared.b16 {%0,%1}, [%2];"
                 : "=r"(r[0]), "=r"(r[1]) : "r"(addr));
}
__device__ __forceinline__ void mma16816(float* c, const uint32_t* a, const uint32_t* b) {
    asm volatile("mma.sync.aligned.m16n8k16.row.col.f32.bf16.bf16.f32 "
                 "{%0,%1,%2,%3}, {%4,%5,%6,%7}, {%8,%9}, {%0,%1,%2,%3};"
                 : "+f"(c[0]), "+f"(c[1]), "+f"(c[2]), "+f"(c[3])
                 : "r"(a[0]), "r"(a[1]), "r"(a[2]), "r"(a[3]),
                   "r"(b[0]), "r"(b[1]));
}
#define CP_ASYNC16(sdst, gsrc) \
    asm volatile("cp.async.cg.shared.global [%0], [%1], 16;" :: "r"(sdst), "l"(gsrc))
#define CP_COMMIT() asm volatile("cp.async.commit_group;" ::: "memory")
#define CP_WAIT1()  asm volatile("cp.async.wait_group 1;" ::: "memory")

__device__ __forceinline__ float sigmoidf_(float x) { return 1.0f / (1.0f + __expf(-x)); }
__device__ __forceinline__ float tanhf_(float x) { return 2.0f / (1.0f + __expf(-2.0f * x)) - 1.0f; }
__device__ __forceinline__ float sel4(float v0, float v1, float v2, float v3, int i) {
    float r = v0;
    if (i == 1) r = v1; else if (i == 2) r = v2; else if (i == 3) r = v3;
    return r;
}

// ---------------------------------------------------------------------------
// Zero h buffers + barrier counter
// ---------------------------------------------------------------------------
__global__ void zero_state_kernel() {
    int i = blockIdx.x * blockDim.x + threadIdx.x;
    if (i == 0) g_bar = 0u;
    const uint4 z = make_uint4(0, 0, 0, 0);
    if (i < (int)(sizeof(g_hhi) / 16)) {
        reinterpret_cast<uint4*>(&g_hhi[0][0])[i] = z;
        reinterpret_cast<uint4*>(&g_hlo[0][0])[i] = z;
    }
}

// ---------------------------------------------------------------------------
// fp32 -> bf16 hi/lo split
// ---------------------------------------------------------------------------
__global__ void split_kernel(const float* __restrict__ src,
                             __nv_bfloat16* __restrict__ hi,
                             __nv_bfloat16* __restrict__ lo, int n4) {
    int i = blockIdx.x * blockDim.x + threadIdx.x;
    int stride = gridDim.x * blockDim.x;
    for (; i < n4; i += stride) {
        float4 v = reinterpret_cast<const float4*>(src)[i];
        __nv_bfloat16 h[4], l[4];
        float vv[4] = {v.x, v.y, v.z, v.w};
#pragma unroll
        for (int k = 0; k < 4; k++) {
            h[k] = __float2bfloat16_rn(vv[k]);
            l[k] = __float2bfloat16_rn(vv[k] - __bfloat162float(h[k]));
        }
        reinterpret_cast<uint2*>(hi)[i] = *reinterpret_cast<uint2*>(h);
        reinterpret_cast<uint2*>(lo)[i] = *reinterpret_cast<uint2*>(l);
    }
}

__global__ void split_out0_kernel(int n4) {
    int i = blockIdx.x * blockDim.x + threadIdx.x;
    int stride = gridDim.x * blockDim.x;
    for (; i < n4; i += stride) {
        float4 v = reinterpret_cast<const float4*>(g_out0)[i];
        __nv_bfloat16 h[4], l[4];
        float vv[4] = {v.x, v.y, v.z, v.w};
#pragma unroll
        for (int k = 0; k < 4; k++) {
            h[k] = __float2bfloat16_rn(vv[k]);
            l[k] = __float2bfloat16_rn(vv[k] - __bfloat162float(h[k]));
        }
        reinterpret_cast<uint2*>(g_Ahi)[i] = *reinterpret_cast<uint2*>(h);
        reinterpret_cast<uint2*>(g_Alo)[i] = *reinterpret_cast<uint2*>(l);
    }
}

// ---------------------------------------------------------------------------
// bf16x3 GEMM via mma.sync (unchanged from round 3, validated)
// ---------------------------------------------------------------------------
#define KSTG       32
#define NSTAGES    (HID / KSTG)
#define PITCH_B    80
#define REG_BYTES  (128 * PITCH_B)
#define STG_BYTES  (4 * REG_BYTES)
#define GEMM_SMEM  (2 * STG_BYTES)

__device__ __forceinline__ void stage_load(uint32_t sbase, int s, int m0, int n0,
                                           int tid) {
    const int kt = s * KSTG;
    const uint32_t dst = sbase + (s & 1) * STG_BYTES;
#pragma unroll
    for (int r = 0; r < 4; r++) {
        const __nv_bfloat16* src =
            (r == 0) ? g_Ahi : (r == 1) ? g_Alo : (r == 2) ? g_Whi : g_Wlo;
        const int rb = (r < 2) ? m0 : n0;
#pragma unroll
        for (int j = 0; j < 2; j++) {
            const int chunk = tid + j * 256;
            const int row = chunk >> 2;
            const int kc = chunk & 3;
            const void* g = src + (size_t)(rb + row) * HID + kt + kc * 8;
            const uint32_t sd = dst + r * REG_BYTES + row * PITCH_B + kc * 16;
            CP_ASYNC16(sd, g);
        }
    }
}

__global__ __launch_bounds__(256, 1) void mma_gemm_kernel(
    const float* __restrict__ bias1, const float* __restrict__ bias2)
{
    extern __shared__ char dsm[];
    __shared__ float s_bias[128];

    const int tid = threadIdx.x;
    const int wid = tid >> 5;
    const int lane = tid & 31;
    const int m0 = blockIdx.x * 128;
    const int n0 = blockIdx.y * 128;
    const int wm = (wid & 3) * 32;
    const int wn = (wid >> 2) * 64;

    const uint32_t sbase = smem_u32(dsm);

    if (tid < 128) s_bias[tid] = bias1[n0 + tid] + bias2[n0 + tid];

    float acc[2][8][4];
#pragma unroll
    for (int ma = 0; ma < 2; ma++)
#pragma unroll
        for (int nb = 0; nb < 8; nb++)
#pragma unroll
            for (int c = 0; c < 4; c++) acc[ma][nb][c] = 0.f;

    stage_load(sbase, 0, m0, n0, tid);
    CP_COMMIT();

    for (int s = 0; s < NSTAGES; s++) {
        if (s + 1 < NSTAGES) stage_load(sbase, s + 1, m0, n0, tid);
        CP_COMMIT();
        CP_WAIT1();
        __syncthreads();

        const uint32_t sb = sbase + (s & 1) * STG_BYTES;
        const uint32_t aHi = sb;
        const uint32_t aLo = sb + REG_BYTES;
        const uint32_t wHi = sb + 2 * REG_BYTES;
        const uint32_t wLo = sb + 3 * REG_BYTES;

#pragma unroll
        for (int kk = 0; kk < 2; kk++) {
            const uint32_t aoff = (lane & 15) * PITCH_B + (lane >> 4) * 16 + kk * 32;
            const uint32_t boff = (lane & 7) * PITCH_B + ((lane >> 3) & 1) * 16 + kk * 32;

            uint32_t ahi[2][4], alo[2][4];
            ldsm4(ahi[0], aHi + (wm + 0) * PITCH_B + aoff);
            ldsm4(ahi[1], aHi + (wm + 16) * PITCH_B + aoff);
            ldsm4(alo[0], aLo + (wm + 0) * PITCH_B + aoff);
            ldsm4(alo[1], aLo + (wm + 16) * PITCH_B + aoff);

            uint32_t whi[8][2], wlo[8][2];
#pragma unroll
            for (int nb = 0; nb < 8; nb++) {
                ldsm2(whi[nb], wHi + (wn + nb * 8) * PITCH_B + boff);
                ldsm2(wlo[nb], wLo + (wn + nb * 8) * PITCH_B + boff);
            }

#pragma unroll
            for (int ma = 0; ma < 2; ma++)
#pragma unroll
                for (int nb = 0; nb < 8; nb++) {
                    mma16816(acc[ma][nb], ahi[ma], whi[nb]);
                    mma16816(acc[ma][nb], ahi[ma], wlo[nb]);
                    mma16816(acc[ma][nb], alo[ma], whi[nb]);
                }
        }
        __syncthreads();
    }

#pragma unroll
    for (int ma = 0; ma < 2; ma++) {
        const int row = m0 + wm + ma * 16 + (lane >> 2);
#pragma unroll
        for (int nb = 0; nb < 8; nb++) {
            const int cloc = wn + nb * 8 + (lane & 3) * 2;
            const int col = n0 + cloc;
            const float b0 = s_bias[cloc], b1 = s_bias[cloc + 1];
            float2 v0 = make_float2(acc[ma][nb][0] + b0, acc[ma][nb][1] + b1);
            float2 v1 = make_float2(acc[ma][nb][2] + b0, acc[ma][nb][3] + b1);
            *reinterpret_cast<float2*>(&g_proj[(size_t)row * G4 + col]) = v0;
            *reinterpret_cast<float2*>(&g_proj[(size_t)(row + 8) * G4 + col]) = v1;
        }
    }
}

// ---------------------------------------------------------------------------
// Persistent LSTM recurrence via mma.sync bf16x3.
// 128 blocks x 128 threads. Block owns 8 hidden units = 32 gate rows (r=u*4+g).
// W_hh slice bf16 hi/lo SMEM-resident (pitch 2064). Per step: C[32,64] =
// W(A-operand) x h(B-operand), h staged from global bf16 hi/lo in 128-k chunks
// (cp.async double buffer). Gate transpose via 3-round shfl rotation.
// ---------------------------------------------------------------------------
#define PW       2064                    // W row pitch bytes (1024*2 + 16)
#define PH       272                     // h stage row pitch bytes (128*2 + 16)
#define HS_BUF   (2 * 64 * PH)           // one chunk buffer (hi+lo) = 34816
#define REC_SMEM (64 * PW + 2 * HS_BUF)  // 132096 + 69632 = 201728

__device__ __forceinline__ void stage_h(uint32_t smH, int sbit, int c) {
    const __nv_bfloat16* hh = g_hhi[sbit];
    const __nv_bfloat16* hl = g_hlo[sbit];
    const int kt = c * 128;
    const uint32_t dst = smH + (c & 1) * HS_BUF;
    const int tid = threadIdx.x;
#pragma unroll
    for (int t = 0; t < 16; t++) {
        const int idx = tid + t * 128;        // 0..2047
        const int half = idx >> 10;           // 0=hi 1=lo
        const int row = (idx >> 4) & 63;      // batch row
        const int kc = idx & 15;              // 16B column chunk
        const __nv_bfloat16* g = (half ? hl : hh) + row * HID + kt + kc * 8;
        CP_ASYNC16(dst + half * (64 * PH) + row * PH + kc * 16, g);
    }
}

__global__ __launch_bounds__(128, 1) void lstm_mma_kernel(
    const float* __restrict__ W,   // W_hh [4096,1024] fp32
    float* __restrict__ out,       // layer output (nullptr -> g_out0)
    float* __restrict__ hn,
    float* __restrict__ cn)
{
    extern __shared__ char sm[];
    const uint32_t smW = smem_u32(sm);
    const uint32_t smWlo = smW + 32 * PW;
    const uint32_t smH = smW + 64 * PW;

    float* outp = out ? out : g_out0;

    const int tid = threadIdx.x;
    const int wid = tid >> 5;
    const int lane = tid & 31;
    const int blk = blockIdx.x;
    const int q = (lane >> 2) & 3;   // gate-bits of lane
    const int t2 = lane >> 4;        // unit sub-index
    const int sL = lane & 3;         // batch col pair

    // Stage W_hh slice: smem row r = u*4+g  <-  W[(g*HID + blk*8 + u)][k]
    for (int r = wid; r < 32; r += 4) {
        const int u = r >> 2, g = r & 3;
        const float* src = W + ((size_t)(g * HID + blk * 8 + u)) * HID;
        __nv_bfloat16* dh = reinterpret_cast<__nv_bfloat16*>(sm + r * PW);
        __nv_bfloat16* dl = reinterpret_cast<__nv_bfloat16*>(sm + 32 * PW + r * PW);
        for (int k = lane; k < HID; k += 32) {
            float v = src[k];
            __nv_bfloat16 h = __float2bfloat16_rn(v);
            dh[k] = h;
            dl[k] = __float2bfloat16_rn(v - __bfloat162float(h));
        }
    }
    __syncthreads();

    float cst[4] = {0.f, 0.f, 0.f, 0.f};   // c state per (mt,nt) combo

    for (int s = 0; s < SEQ; s++) {
        // Prefetch x-projection for this thread's 4 (unit,batch) combos x 4 gates
        float pv[4][4];
#pragma unroll
        for (int mt = 0; mt < 2; mt++)
#pragma unroll
            for (int nt = 0; nt < 2; nt++) {
                const int combo = mt * 2 + nt;
                const int U = mt * 4 + t2 + 2 * (q >> 1);
                const int jg = blk * 8 + U;
                const int bcol = wid * 16 + nt * 8 + sL * 2 + (q & 1);
                const float* pb = g_proj + ((size_t)(s * BATCH + bcol)) * G4 + jg;
#pragma unroll
                for (int g = 0; g < 4; g++)
                    pv[combo][g] = __ldg(&pb[g * HID]);
            }

        float acc[2][2][4];
#pragma unroll
        for (int mt = 0; mt < 2; mt++)
#pragma unroll
            for (int nt = 0; nt < 2; nt++)
#pragma unroll
                for (int c = 0; c < 4; c++) acc[mt][nt][c] = 0.f;

        stage_h(smH, s & 1, 0);
        CP_COMMIT();

        for (int c = 0; c < 8; c++) {
            if (c + 1 < 8) stage_h(smH, s & 1, c + 1);
            CP_COMMIT();
            CP_WAIT1();
            __syncthreads();

            const uint32_t hb = smH + (c & 1) * HS_BUF;
#pragma unroll
            for (int kk = 0; kk < 8; kk++) {
                const uint32_t aoff = (lane & 15) * PW + (lane >> 4) * 16
                                    + c * 256 + kk * 32;
                uint32_t awh[2][4], awl[2][4];
                ldsm4(awh[0], smW + aoff);
                ldsm4(awh[1], smW + 16 * PW + aoff);
                ldsm4(awl[0], smWlo + aoff);
                ldsm4(awl[1], smWlo + 16 * PW + aoff);

                const uint32_t boff = (lane & 7) * PH + ((lane >> 3) & 1) * 16
                                    + kk * 32 + wid * 16 * PH;
                uint32_t bh[2][2], bl[2][2];
                ldsm2(bh[0], hb + boff);
                ldsm2(bh[1], hb + 8 * PH + boff);
                ldsm2(bl[0], hb + 64 * PH + boff);
                ldsm2(bl[1], hb + 64 * PH + 8 * PH + boff);

#pragma unroll
                for (int mt = 0; mt < 2; mt++)
#pragma unroll
                    for (int nt = 0; nt < 2; nt++) {
                        mma16816(acc[mt][nt], awh[mt], bh[nt]);
                        mma16816(acc[mt][nt], awh[mt], bl[nt]);
                        mma16816(acc[mt][nt], awl[mt], bh[nt]);
                    }
            }
            __syncthreads();
        }

        // Elementwise: transpose gates across lanes (bits 2-3), update c,h
        const int wbuf = (s + 1) & 1;
#pragma unroll
        for (int mt = 0; mt < 2; mt++)
#pragma unroll
            for (int nt = 0; nt < 2; nt++) {
                const int combo = mt * 2 + nt;
                const float v0 = acc[mt][nt][0], v1 = acc[mt][nt][1];
                const float v2 = acc[mt][nt][2], v3 = acc[mt][nt][3];
                float w0, w1, w2, w3;
                {   // j = 0 (own value)
                    const float r = sel4(v0, v1, v2, v3, q);
                    if (q == 0) w0 = r; else if (q == 1) w1 = r;
                    else if (q == 2) w2 = r; else w3 = r;
                }
#pragma unroll
                for (int j = 1; j < 4; j++) {
                    const int si = (q + j) & 3;
                    const int d = (q - j) & 3;
                    const float send = sel4(v0, v1, v2, v3, si);
                    const int src = (lane & 19) | (d << 2);
                    const float r = __shfl_sync(0xffffffffu, send, src);
                    if (d == 0) w0 = r; else if (d == 1) w1 = r;
                    else if (d == 2) w2 = r; else w3 = r;
                }

                const float gi = sigmoidf_(w0 + pv[combo][0]);
                const float gf = sigmoidf_(w1 + pv[combo][1]);
                const float gg = tanhf_  (w2 + pv[combo][2]);
                const float go = sigmoidf_(w3 + pv[combo][3]);
                const float cnew = gf * cst[combo] + gi * gg;
                cst[combo] = cnew;
                const float hv = go * tanhf_(cnew);

                const int U = mt * 4 + t2 + 2 * (q >> 1);
                const int jg = blk * 8 + U;
                const int bcol = wid * 16 + nt * 8 + sL * 2 + (q & 1);

                const __nv_bfloat16 hh = __float2bfloat16_rn(hv);
                g_hhi[wbuf][bcol * HID + jg] = hh;
                g_hlo[wbuf][bcol * HID + jg] =
                    __float2bfloat16_rn(hv - __bfloat162float(hh));
                outp[((size_t)s * BATCH + bcol) * HID + jg] = hv;
                if (s == SEQ - 1) {
                    hn[bcol * HID + jg] = hv;
                    cn[bcol * HID + jg] = cnew;
                }
            }

        // Grid barrier
        __threadfence();
        __syncthreads();
        if (tid == 0) {
            atomicAdd(&g_bar, 1u);
            const unsigned target = (unsigned)(s + 1) * gridDim.x;
            while (atomicAdd(&g_bar, 0u) < target) __nanosleep(64);
            __threadfence();
        }
        __syncthreads();
    }
}

// ---------------------------------------------------------------------------
// Launch
// ---------------------------------------------------------------------------
extern "C" void kernel_launch(void* const* d_in, const int* in_sizes, int n_in,
                              void* d_out, int out_size)
{
    const float* x     = (const float*)d_in[0];
    const float* Wih0  = (const float*)d_in[1];
    const float* Whh0  = (const float*)d_in[2];
    const float* bih0  = (const float*)d_in[3];
    const float* bhh0  = (const float*)d_in[4];
    const float* Wih1  = (const float*)d_in[5];
    const float* Whh1  = (const float*)d_in[6];
    const float* bih1  = (const float*)d_in[7];
    const float* bhh1  = (const float*)d_in[8];

    float* out1 = (float*)d_out;
    float* hn   = out1 + (size_t)SEQ * BATCH * HID;
    float* cn   = hn + 2 * BATCH * HID;

    cudaFuncSetAttribute(mma_gemm_kernel,
                         cudaFuncAttributeMaxDynamicSharedMemorySize, GEMM_SMEM);
    cudaFuncSetAttribute(lstm_mma_kernel,
                         cudaFuncAttributeMaxDynamicSharedMemorySize, REC_SMEM);

    __nv_bfloat16 *Ahi, *Alo, *Whi, *Wlo;
    cudaGetSymbolAddress((void**)&Ahi, g_Ahi);
    cudaGetSymbolAddress((void**)&Alo, g_Alo);
    cudaGetSymbolAddress((void**)&Whi, g_Whi);
    cudaGetSymbolAddress((void**)&Wlo, g_Wlo);

    dim3 mgrid(MROWS / 128, G4 / 128);   // (256, 32), m fastest

    // ---- Layer 0 ----
    split_kernel<<<2048, 256>>>(x, Ahi, Alo, (MROWS * HID) / 4);
    split_kernel<<<512, 256>>>(Wih0, Whi, Wlo, (G4 * HID) / 4);
    zero_state_kernel<<<128, 256>>>();
    mma_gemm_kernel<<<mgrid, 256, GEMM_SMEM>>>(bih0, bhh0);
    lstm_mma_kernel<<<128, 128, REC_SMEM>>>(Whh0, nullptr, hn, cn);

    // ---- Layer 1 ----
    split_out0_kernel<<<2048, 256>>>((MROWS * HID) / 4);
    split_kernel<<<512, 256>>>(Wih1, Whi, Wlo, (G4 * HID) / 4);
    zero_state_kernel<<<128, 256>>>();
    mma_gemm_kernel<<<mgrid, 256, GEMM_SMEM>>>(bih1, bhh1);
    lstm_mma_kernel<<<128, 128, REC_SMEM>>>(Whh1, out1,
                                            hn + BATCH * HID,
                                            cn + BATCH * HID);
}